// round 5
// baseline (speedup 1.0000x reference)
#include <cuda_runtime.h>
#include <cuda_bf16.h>
#include <math.h>

// Problem shape (fixed by the reference):
//   q,k,v: [H, N, D] fp32   adj: [H, N, N] fp32   alpha,beta: [H] fp32
//   out:   [H, N, D] fp32
#define HH 8
#define NN 4096
#define DD 64
#define ROWS 32                 // rows per block for the correction path
#define NTHREADS 256
#define TOTAL4 (HH * NN * DD / 4)        // 2097152 float4 elements
#define GRID_BLOCKS ((NN / ROWS) * HH)   // 1024
#define COPY_STRIDE (GRID_BLOCKS * NTHREADS)  // 262144
#define COPY_ITERS (TOTAL4 / COPY_STRIDE)     // 8

// ---------------------------------------------------------------------------
// Math identity:
//   P = softmax(Q K^T * scale + adj)
//   out[h,n,:] = beta[h]*(P[h,n,:] @ V[h]) + (alpha[h] - beta[h]*P[h,n,n])*v[h,n,:]
//
// Race-free split across the two phases:
//   phase 1 (flat grid-stride, 8 float4/thread): writes out = alpha*v ONLY for
//           heads with beta==0 (for those heads this is the exact full answer).
//   phase 2 (per-row-slab, only if beta[h] != 0): writes the COMPLETE value
//           b*(P@V) + (a - b*P_rr)*v_r  -- no read-modify-write of out, so no
//           dependence on phase-1 ordering across blocks.
// Each output element is written by exactly one phase -> deterministic.
// ---------------------------------------------------------------------------
__global__ void __launch_bounds__(NTHREADS)
fused_adj_attention_kernel(const float* __restrict__ q,
                           const float* __restrict__ k,
                           const float* __restrict__ v,
                           const float* __restrict__ adj,
                           const float* __restrict__ alpha,
                           const float* __restrict__ beta,
                           float* __restrict__ out) {
    const int h_blk = blockIdx.y;
    const int tid   = threadIdx.x;

    // ---- phase 1: flat copy out = alpha*v (beta==0 heads), MLP=8 ----
    {
        const int bid = blockIdx.y * gridDim.x + blockIdx.x;
        const int i0  = bid * NTHREADS + tid;
        const float4* __restrict__ v4 = (const float4*)v;
        float4*       __restrict__ o4 = (float4*)out;

        float4 t[COPY_ITERS];
        float  a[COPY_ITERS];
        bool   wr[COPY_ITERS];
        #pragma unroll
        for (int j = 0; j < COPY_ITERS; j++) {
            const int i = i0 + j * COPY_STRIDE;
            t[j] = v4[i];                           // 8 batched independent loads
            const int h = i >> 16;                  // i / (N*D/4) = i / 65536
            a[j]  = __ldg(&alpha[h]);
            wr[j] = (__ldg(&beta[h]) == 0.0f);
        }
        #pragma unroll
        for (int j = 0; j < COPY_ITERS; j++) {
            if (wr[j]) {
                const int i = i0 + j * COPY_STRIDE;
                float4 r = t[j];
                r.x *= a[j]; r.y *= a[j]; r.z *= a[j]; r.w *= a[j];
                o4[i] = r;
            }
        }
    }

    const float b = __ldg(&beta[h_blk]);
    if (b == 0.0f) return;   // exact: correction term is identically zero

    // ---- phase 2: full-softmax path, writes complete out values ----
    __shared__ float s[NN];        // 16 KB: scores -> exp weights, one row
    __shared__ float qs[DD];
    __shared__ float red[NTHREADS];

    const int   h     = h_blk;
    const int   row0  = blockIdx.x * ROWS;
    const float a     = __ldg(&alpha[h]);
    const float scale = rsqrtf((float)DD);
    const float* kh = k + (long)h * NN * DD;
    const float* vh = v + (long)h * NN * DD;

    for (int rr = 0; rr < ROWS; rr++) {
        const int r = row0 + rr;
        if (tid < DD) qs[tid] = q[((long)h * NN + r) * DD + tid];
        __syncthreads();

        const float* adjr = adj + ((long)h * NN + r) * NN;

        // scores + running max
        float lmax = -INFINITY;
        for (int m = tid; m < NN; m += NTHREADS) {
            const float* km = kh + (long)m * DD;
            float dot = 0.f;
            #pragma unroll 16
            for (int d = 0; d < DD; d++) dot = fmaf(qs[d], km[d], dot);
            float val = dot * scale + adjr[m];
            s[m] = val;
            lmax = fmaxf(lmax, val);
        }
        red[tid] = lmax; __syncthreads();
        for (int o = NTHREADS / 2; o > 0; o >>= 1) {
            if (tid < o) red[tid] = fmaxf(red[tid], red[tid + o]);
            __syncthreads();
        }
        const float mx = red[0]; __syncthreads();

        // exp + sum
        float lsum = 0.f;
        for (int m = tid; m < NN; m += NTHREADS) {
            float e = expf(s[m] - mx);
            s[m] = e;
            lsum += e;
        }
        red[tid] = lsum; __syncthreads();
        for (int o = NTHREADS / 2; o > 0; o >>= 1) {
            if (tid < o) red[tid] += red[tid + o];
            __syncthreads();
        }
        const float inv = 1.0f / red[0]; __syncthreads();
        const float prr = s[r] * inv;    // P[r,r]

        // weighted V accumulate: thread t -> dim d = t&63, group g = t>>6
        const int d = tid & 63, g = tid >> 6;
        float acc = 0.f;
        for (int m = g; m < NN; m += 4) acc += s[m] * vh[(long)m * DD + d];
        red[tid] = acc; __syncthreads();
        if (g == 0) {
            float tot = red[d] + red[64 + d] + red[128 + d] + red[192 + d];
            // complete value: b*(P@V) + (a - b*P_rr)*v_r
            out[((long)h * NN + r) * DD + d] =
                b * tot * inv + (a - b * prr) * vh[(long)r * DD + d];
        }
        __syncthreads();
    }
}

extern "C" void kernel_launch(void* const* d_in, const int* in_sizes, int n_in,
                              void* d_out, int out_size) {
    const float* q     = (const float*)d_in[0];
    const float* k     = (const float*)d_in[1];
    const float* v     = (const float*)d_in[2];
    const float* adj   = (const float*)d_in[3];
    const float* alpha = (const float*)d_in[4];
    const float* beta  = (const float*)d_in[5];
    float* out = (float*)d_out;

    dim3 grid(NN / ROWS, HH);   // (128, 8) = 1024 blocks
    fused_adj_attention_kernel<<<grid, NTHREADS>>>(q, k, v, adj, alpha, beta, out);
}